// round 14
// baseline (speedup 1.0000x reference)
#include <cuda_runtime.h>

// Inputs (metadata order):
//  0: link_pos_seq   [1024,32,8,3]    f32
//  1: link_rot_seq   [1024,32,8,3,3]  f32
//  2: sphere_centers [8,8,3]          f32
//  3: sphere_radii   [8,8]            f32
//  4: sdf_grid       [256,256,256]    f32
//  5: weight         scalar           f32
// Output: [1024,32] f32

#define GRID_N 256
#define N_LINKS 8
#define N_SPH 8
#define TB 256
#define NWARP (TB / 32)

// L2-only gather (no L1 allocation): random 4B picks have zero L1 reuse.
__device__ __forceinline__ float ldcg(const float* p) {
    float v;
    asm volatile("ld.global.cg.f32 %0, [%1];" : "=f"(v) : "l"(p));
    return v;
}

// Faithfully-rounded t/0.01 (mul + 2 fma Newton residual correction).
__device__ __forceinline__ float div001(float t) {
    const float q0 = t * 100.0f;
    return fmaf(fmaf(-0.01f, q0, t), 100.0f, q0);
}

__device__ __forceinline__ int vox(float t) {
    int i = (int)floorf(div001(t + 1.28f));
    return min(max(i, 0), GRID_N - 1);
}

__global__ __launch_bounds__(TB, 8)
void voxel_collision_kernel(const float* __restrict__ pos,
                            const float* __restrict__ rot,
                            const float* __restrict__ cen,
                            const float* __restrict__ rad,
                            const float* __restrict__ sdf,
                            const float* __restrict__ wptr,
                            float* __restrict__ out) {
    __shared__ float s_rot[NWARP][288];            // 9 floats x 32 lanes per warp
    __shared__ float s_pos[NWARP][96];             // 3 floats x 32 lanes per warp
    __shared__ float s_cen[N_LINKS * N_SPH * 3];   // 768 B
    __shared__ float s_rad[N_LINKS * N_SPH];       // 256 B

    const int tid  = threadIdx.x;
    const int w    = tid >> 5;
    const int lane = tid & 31;

    if (tid < N_LINKS * N_SPH * 3) s_cen[tid] = cen[tid];
    if (tid < N_LINKS * N_SPH)     s_rad[tid] = rad[tid];
    __syncthreads();   // covers s_cen/s_rad only; rot/pos slabs are warp-private

    const int gwarp = blockIdx.x * TB + w * 32;
    const int g = gwarp + lane;
    const int l = g & 7;

    // ---- warp-cooperative coalesced staging: 12 LDGs, 1 line each ----
    {
        const float* slabR = rot + (size_t)gwarp * 9;   // 288 consecutive floats
        const float* slabP = pos + (size_t)gwarp * 3;   // 96 consecutive floats
        float tR[9], tP[3];
        #pragma unroll
        for (int i = 0; i < 9; i++) tR[i] = __ldg(slabR + i * 32 + lane);
        #pragma unroll
        for (int i = 0; i < 3; i++) tP[i] = __ldg(slabP + i * 32 + lane);
        #pragma unroll
        for (int i = 0; i < 9; i++) s_rot[w][i * 32 + lane] = tR[i];
        #pragma unroll
        for (int i = 0; i < 3; i++) s_pos[w][i * 32 + lane] = tP[i];
        __syncwarp();
    }

    // stride-9 / stride-3 LDS: gcd(9,32)=gcd(3,32)=1 -> conflict-free
    const float r00 = s_rot[w][lane * 9 + 0], r01 = s_rot[w][lane * 9 + 1], r02 = s_rot[w][lane * 9 + 2];
    const float r10 = s_rot[w][lane * 9 + 3], r11 = s_rot[w][lane * 9 + 4], r12 = s_rot[w][lane * 9 + 5];
    const float r20 = s_rot[w][lane * 9 + 6], r21 = s_rot[w][lane * 9 + 7], r22 = s_rot[w][lane * 9 + 8];
    const float px = s_pos[w][lane * 3 + 0], py = s_pos[w][lane * 3 + 1], pz = s_pos[w][lane * 3 + 2];

    const float* lc = s_cen + l * (N_SPH * 3);
    const float* lr = s_rad + l * N_SPH;

    // 8 mutually independent gathers (ptxas front-batches the LDGs)
    float m = -3.402823466e+38f;
    #pragma unroll
    for (int s = 0; s < N_SPH; s++) {
        const float cx = lc[s * 3 + 0];
        const float cy = lc[s * 3 + 1];
        const float cz = lc[s * 3 + 2];
        const float x = fmaf(r00, cx, fmaf(r01, cy, fmaf(r02, cz, px)));
        const float y = fmaf(r10, cx, fmaf(r11, cy, fmaf(r12, cz, py)));
        const float z = fmaf(r20, cx, fmaf(r21, cy, fmaf(r22, cz, pz)));
        const float v = ldcg(sdf + ((vox(x) << 16) | (vox(y) << 8) | vox(z)));
        m = fmaxf(m, lr[s] - v);
    }

    // clip(m - 0.01, 0, 0.5) / 0.25
    float res = fminf(fmaxf(m - 0.01f, 0.0f), 0.5f) * 4.0f;

    // sum over the 8 links (adjacent lanes within the warp)
    res += __shfl_xor_sync(0xffffffffu, res, 1);
    res += __shfl_xor_sync(0xffffffffu, res, 2);
    res += __shfl_xor_sync(0xffffffffu, res, 4);

    if (l == 0) out[g >> 3] = __ldg(wptr) * res;
}

extern "C" void kernel_launch(void* const* d_in, const int* in_sizes, int n_in,
                              void* d_out, int out_size) {
    const float* pos = (const float*)d_in[0];
    const float* rot = (const float*)d_in[1];
    const float* cen = (const float*)d_in[2];
    const float* rad = (const float*)d_in[3];
    const float* sdf = (const float*)d_in[4];
    const float* w   = (const float*)d_in[5];
    float* out = (float*)d_out;

    // Request max shared-memory carveout so 8 blocks x 13.3KB fit per SM
    // (R2/R6 occupancy collapses are consistent with a small default carveout).
    // Host-side attribute set; idempotent, no allocation, graph-capture safe.
    cudaFuncSetAttribute(voxel_collision_kernel,
                         cudaFuncAttributePreferredSharedMemoryCarveout,
                         cudaSharedmemCarveoutMaxShared);

    voxel_collision_kernel<<<1024, TB>>>(pos, rot, cen, rad, sdf, w, out);
}

// round 15
// speedup vs baseline: 1.4147x; 1.4147x over previous
#include <cuda_runtime.h>

// Inputs (metadata order):
//  0: link_pos_seq   [1024,32,8,3]    f32
//  1: link_rot_seq   [1024,32,8,3,3]  f32
//  2: sphere_centers [8,8,3]          f32
//  3: sphere_radii   [8,8]            f32
//  4: sdf_grid       [256,256,256]    f32
//  5: weight         scalar           f32
// Output: [1024,32] f32

#define GRID_N 256
#define N_LINKS 8
#define N_SPH 8

// L2-only gather (no L1 allocation): random 4B picks from a 64MB grid have
// zero L1 reuse, so skip the L1 fill/tag work on the bottleneck pipe.
__device__ __forceinline__ float ldcg(const float* p) {
    float v;
    asm volatile("ld.global.cg.f32 %0, [%1];" : "=f"(v) : "l"(p));
    return v;
}

// Faithfully-rounded t/0.01 in 3 instructions (mul + 2 fma Newton residual
// correction). <=1ulp from IEEE division; floor flips only at already-rare
// boundary cases (rel_err measured bit-identical to IEEE path: 1.95e-4).
__device__ __forceinline__ float div001(float t) {
    const float q0 = t * 100.0f;
    return fmaf(fmaf(-0.01f, q0, t), 100.0f, q0);
}

__device__ __forceinline__ int vox(float t) {
    int i = (int)floorf(div001(t + 1.28f));
    return min(max(i, 0), GRID_N - 1);
}

__global__ __launch_bounds__(256, 8)
void voxel_collision_kernel(const float* __restrict__ pos,
                            const float* __restrict__ rot,
                            const float* __restrict__ cen,
                            const float* __restrict__ rad,
                            const float* __restrict__ sdf,
                            const float* __restrict__ wptr,
                            float* __restrict__ out) {
    __shared__ float s_cen[N_LINKS * N_SPH * 3];   // 192 floats
    __shared__ float s_rad[N_LINKS * N_SPH];       // 64 floats

    const int tid = threadIdx.x;
    if (tid < N_LINKS * N_SPH * 3) s_cen[tid] = cen[tid];
    if (tid < N_LINKS * N_SPH)     s_rad[tid] = rad[tid];
    __syncthreads();

    const int g = blockIdx.x * 256 + tid;          // 0 .. 262143 = bh*8 + l
    const int l = g & 7;

    // Load rotation (9 consecutive floats) and position (3 consecutive floats).
    const float* R = rot + (size_t)g * 9;
    const float r00 = __ldg(R + 0), r01 = __ldg(R + 1), r02 = __ldg(R + 2);
    const float r10 = __ldg(R + 3), r11 = __ldg(R + 4), r12 = __ldg(R + 5);
    const float r20 = __ldg(R + 6), r21 = __ldg(R + 7), r22 = __ldg(R + 8);
    const float* P = pos + (size_t)g * 3;
    const float px = __ldg(P + 0), py = __ldg(P + 1), pz = __ldg(P + 2);

    const float* lc = s_cen + l * (N_SPH * 3);
    const float* lr = s_rad + l * N_SPH;

    float m = -3.402823466e+38f;
    #pragma unroll
    for (int s = 0; s < N_SPH; s++) {
        const float cx = lc[s * 3 + 0];
        const float cy = lc[s * 3 + 1];
        const float cz = lc[s * 3 + 2];
        // world point = R @ c + p
        const float x = fmaf(r00, cx, fmaf(r01, cy, fmaf(r02, cz, px)));
        const float y = fmaf(r10, cx, fmaf(r11, cy, fmaf(r12, cz, py)));
        const float z = fmaf(r20, cx, fmaf(r21, cy, fmaf(r22, cz, pz)));
        const float v = ldcg(sdf + ((vox(x) << 16) | (vox(y) << 8) | vox(z)));
        m = fmaxf(m, lr[s] - v);
    }

    // threshold / clamp / normalize: clip(m - 0.01, 0, 0.5) / 0.25
    float res = fminf(fmaxf(m - 0.01f, 0.0f), 0.5f) * 4.0f;

    // sum over the 8 links (adjacent lanes within the warp)
    res += __shfl_xor_sync(0xffffffffu, res, 1);
    res += __shfl_xor_sync(0xffffffffu, res, 2);
    res += __shfl_xor_sync(0xffffffffu, res, 4);

    if (l == 0) out[g >> 3] = __ldg(wptr) * res;
}

extern "C" void kernel_launch(void* const* d_in, const int* in_sizes, int n_in,
                              void* d_out, int out_size) {
    const float* pos = (const float*)d_in[0];
    const float* rot = (const float*)d_in[1];
    const float* cen = (const float*)d_in[2];
    const float* rad = (const float*)d_in[3];
    const float* sdf = (const float*)d_in[4];
    const float* w   = (const float*)d_in[5];
    float* out = (float*)d_out;

    // 1024*32*8 = 262144 threads, 256 per block
    voxel_collision_kernel<<<1024, 256>>>(pos, rot, cen, rad, sdf, w, out);
}